// round 2
// baseline (speedup 1.0000x reference)
#include <cuda_runtime.h>
#include <cuda_fp16.h>
#include <cstdint>

// ============================================================================
// out[8192,2048] = x[8192,2048] @ W[2048,2048]^T + b   (fp32 in/out)
//
// Toolchain constraint (discovered R1): PTX is assembled with .target sm_103
// (no 'a'), which rejects tcgen05.ld/wait/dealloc -> TMEM results unreadable.
// So: single-pass fp16 mma.sync.m16n8k16 (plain-target legal), fp32 accum.
// Error model: ~3e-4 norm rel err, 3.5x margin under the 1e-3 threshold.
// ============================================================================

#define DIM      2048
#define M_TOTAL  8192
#define BM       128
#define BN       256
#define BK       64
#define THREADS  512
#define STAGES   3
#define KITERS   (DIM / BK)          // 32

// fp16 scratch (allocation-free: __device__ globals)
__device__ __half g_Xh[(size_t)M_TOTAL * DIM];   // 32 MB
__device__ __half g_Wh[(size_t)DIM * DIM];       //  8 MB

// smem: per stage A[128x64]f16 = 16KB, B[256x64]f16 = 32KB
#define A_BYTES     16384
#define STAGE_BYTES 49152
#define SMEM_BYTES  (STAGES * STAGE_BYTES)       // 147456

// ---------------------------------------------------------------------------
__device__ __forceinline__ uint32_t smem_u32(const void* p) {
    uint32_t a;
    asm("{ .reg .u64 t; cvta.to.shared.u64 t, %1; cvt.u32.u64 %0, t; }"
        : "=r"(a) : "l"(p));
    return a;
}
__device__ __forceinline__ uint32_t swz(uint32_t b) {   // SW128: rows of 128B
    return b ^ ((b >> 3) & 0x70);
}
__device__ __forceinline__ void cp16(uint32_t dst, const void* src) {
    asm volatile("cp.async.cg.shared.global [%0], [%1], 16;"
                 :: "r"(dst), "l"(src));
}
#define CP_COMMIT() asm volatile("cp.async.commit_group;" ::: "memory")
#define CP_WAIT2()  asm volatile("cp.async.wait_group 2;" ::: "memory")

#define LDSM4(r0, r1, r2, r3, addr) \
    asm volatile("ldmatrix.sync.aligned.m8n8.x4.shared.b16 {%0,%1,%2,%3}, [%4];" \
                 : "=r"(r0), "=r"(r1), "=r"(r2), "=r"(r3) : "r"(addr))

#define MMA16816(c0, c1, c2, c3, a0, a1, a2, a3, b0, b1) \
    asm volatile("mma.sync.aligned.m16n8k16.row.col.f32.f16.f16.f32 " \
                 "{%0,%1,%2,%3}, {%4,%5,%6,%7}, {%8,%9}, {%0,%1,%2,%3};" \
                 : "+f"(c0), "+f"(c1), "+f"(c2), "+f"(c3) \
                 : "r"(a0), "r"(a1), "r"(a2), "r"(a3), "r"(b0), "r"(b1))

// ============================================================================
// fp32 -> fp16 converters
// ============================================================================
__global__ void __launch_bounds__(256) conv_x_kernel(const float4* __restrict__ in) {
    int i = blockIdx.x * 256 + threadIdx.x;
    float4 v = in[i];
    __half2 lo = __floats2half2_rn(v.x, v.y);
    __half2 hi = __floats2half2_rn(v.z, v.w);
    uint2 p;
    p.x = *reinterpret_cast<uint32_t*>(&lo);
    p.y = *reinterpret_cast<uint32_t*>(&hi);
    reinterpret_cast<uint2*>(g_Xh)[i] = p;
}
__global__ void __launch_bounds__(256) conv_w_kernel(const float4* __restrict__ in) {
    int i = blockIdx.x * 256 + threadIdx.x;
    float4 v = in[i];
    __half2 lo = __floats2half2_rn(v.x, v.y);
    __half2 hi = __floats2half2_rn(v.z, v.w);
    uint2 p;
    p.x = *reinterpret_cast<uint32_t*>(&lo);
    p.y = *reinterpret_cast<uint32_t*>(&hi);
    reinterpret_cast<uint2*>(g_Wh)[i] = p;
}

// ============================================================================
// GEMM: 128x256 CTA tile, 16 warps (2 M x 8 N), warp tile 64x32,
// 3-stage cp.async pipeline, SW128-swizzled smem, ldmatrix + mma.sync fp16.
// ============================================================================
__device__ __forceinline__ void issue_stage(uint32_t sbase, int s, int kc,
                                            int mBase, int nBase, int tid) {
    const uint32_t st = sbase + (uint32_t)s * STAGE_BYTES;
    const __half* Ag = g_Xh + (size_t)mBase * DIM + kc;
    const __half* Bg = g_Wh + (size_t)nBase * DIM + kc;
    // A: 128 rows x 128B = 1024 x 16B chunks; 512 thr x 2
    #pragma unroll
    for (int i = 0; i < 2; i++) {
        int g = i * THREADS + tid;
        int row = g >> 3, c = g & 7;
        cp16(st + swz((uint32_t)(row * 128 + c * 16)),
             Ag + (size_t)row * DIM + c * 8);
    }
    // B: 256 rows x 128B = 2048 x 16B chunks; 512 thr x 4
    #pragma unroll
    for (int i = 0; i < 4; i++) {
        int g = i * THREADS + tid;
        int row = g >> 3, c = g & 7;
        cp16(st + A_BYTES + swz((uint32_t)(row * 128 + c * 16)),
             Bg + (size_t)row * DIM + c * 8);
    }
}

__global__ void __launch_bounds__(THREADS, 1) gemm_fp16_kernel(
    float* __restrict__ out, const float* __restrict__ bias)
{
    extern __shared__ __align__(1024) char smem[];
    const uint32_t sbase = smem_u32(smem);
    const int tid  = threadIdx.x;
    const int lane = tid & 31;
    const int wid  = tid >> 5;
    const int warp_m = wid & 1;        // 2 warps in M
    const int warp_n = wid >> 1;       // 8 warps in N

    const int nBase = blockIdx.x * BN;
    const int mBase = blockIdx.y * BM;

    float c[4][4][4];                  // [mt][nb][4] = 64 fp32 accum
    #pragma unroll
    for (int mt = 0; mt < 4; mt++)
        #pragma unroll
        for (int nb = 0; nb < 4; nb++)
            #pragma unroll
            for (int r = 0; r < 4; r++) c[mt][nb][r] = 0.0f;

    // prologue: prefetch stages 0,1
    issue_stage(sbase, 0, 0, mBase, nBase, tid);
    CP_COMMIT();
    issue_stage(sbase, 1, BK, mBase, nBase, tid);
    CP_COMMIT();

    // precomputed ldmatrix address pieces (byte offsets within the tile)
    const uint32_t a_row  = (uint32_t)(warp_m * 64 + (lane & 15));
    const uint32_t a_blo  = (uint32_t)((lane >> 4) << 4);
    const uint32_t b_row0 = (uint32_t)(warp_n * 32 + ((lane >> 4) << 3) + (lane & 7));
    const uint32_t b_blo  = (uint32_t)(((lane >> 3) & 1) << 4);

    for (int it = 0; it < KITERS; ++it) {
        if (it + 2 < KITERS)
            issue_stage(sbase, (it + 2) % STAGES, (it + 2) * BK, mBase, nBase, tid);
        CP_COMMIT();
        CP_WAIT2();            // stage `it` resident (2 younger groups pending)
        __syncthreads();

        const uint32_t aB = sbase + (uint32_t)(it % STAGES) * STAGE_BYTES;
        const uint32_t bB = aB + A_BYTES;

        #pragma unroll
        for (int k16 = 0; k16 < 4; ++k16) {
            uint32_t a[4][4];
            #pragma unroll
            for (int mt = 0; mt < 4; mt++) {
                uint32_t off = swz(((a_row + mt * 16) << 7) + (uint32_t)(k16 * 32) + a_blo);
                LDSM4(a[mt][0], a[mt][1], a[mt][2], a[mt][3], aB + off);
            }
            uint32_t b[2][4];
            #pragma unroll
            for (int p = 0; p < 2; p++) {
                uint32_t off = swz(((b_row0 + p * 16) << 7) + (uint32_t)(k16 * 32) + b_blo);
                LDSM4(b[p][0], b[p][1], b[p][2], b[p][3], bB + off);
            }
            #pragma unroll
            for (int mt = 0; mt < 4; mt++)
                #pragma unroll
                for (int nb = 0; nb < 4; nb++) {
                    MMA16816(c[mt][nb][0], c[mt][nb][1], c[mt][nb][2], c[mt][nb][3],
                             a[mt][0], a[mt][1], a[mt][2], a[mt][3],
                             b[nb >> 1][(nb & 1) * 2], b[nb >> 1][(nb & 1) * 2 + 1]);
                }
        }
        __syncthreads();       // all warps done with this buffer before it is refilled
    }

    // epilogue: c layout per mma tile: rows lane/4 (+8), cols (lane%4)*2 (+1)
    const int m0 = mBase + warp_m * 64 + (lane >> 2);
    const int n0 = nBase + warp_n * 32 + (lane & 3) * 2;
    #pragma unroll
    for (int mt = 0; mt < 4; mt++) {
        #pragma unroll
        for (int nb = 0; nb < 4; nb++) {
            const int row = m0 + mt * 16;
            const int col = n0 + nb * 8;
            const float2 bb = __ldg(reinterpret_cast<const float2*>(bias + col));
            float2 v0, v1;
            v0.x = c[mt][nb][0] + bb.x;  v0.y = c[mt][nb][1] + bb.y;
            v1.x = c[mt][nb][2] + bb.x;  v1.y = c[mt][nb][3] + bb.y;
            *reinterpret_cast<float2*>(out + (size_t)row * DIM + col) = v0;
            *reinterpret_cast<float2*>(out + (size_t)(row + 8) * DIM + col) = v1;
        }
    }
}

// ============================================================================
// kernel_launch — graph-capturable, allocation-free
// ============================================================================
extern "C" void kernel_launch(void* const* d_in, const int* in_sizes, int n_in,
                              void* d_out, int out_size) {
    const float* x = (const float*)d_in[0];   // [4,2048,2048] -> [8192,2048]
    const float* W = (const float*)d_in[1];   // [2048,2048]
    const float* b = (const float*)d_in[2];   // [2048]
    float* out = (float*)d_out;               // [8192,2048]
    (void)in_sizes; (void)n_in; (void)out_size;

    conv_x_kernel<<<(M_TOTAL * DIM / 4) / 256, 256>>>((const float4*)x);
    conv_w_kernel<<<(DIM * DIM / 4) / 256, 256>>>((const float4*)W);

    cudaFuncSetAttribute(gemm_fp16_kernel,
                         cudaFuncAttributeMaxDynamicSharedMemorySize, SMEM_BYTES);
    dim3 grid(DIM / BN, M_TOTAL / BM);        // (8, 64) = 512 CTAs
    gemm_fp16_kernel<<<grid, THREADS, SMEM_BYTES>>>(out, b);
}

// round 3
// speedup vs baseline: 1.0800x; 1.0800x over previous
#include <cuda_runtime.h>
#include <cuda_fp16.h>
#include <cstdint>

// ============================================================================
// out[8192,2048] = x[8192,2048] @ W[2048,2048]^T + b   (fp32 in/out)
//
// Toolchain constraint (R1): ptxas target is plain sm_103 -> tcgen05.ld/wait
// rejected, so TMEM accumulators are unreadable. Path: fp16 mma.sync.m16n8k16
// with fp32 accumulators (verified rel_err 2.06e-4 in R2, threshold 1e-3).
//
// R3 changes vs R2 (243.8us):
//  - single __syncthreads per K-iter (was 2)          [barrier cost]
//  - 4-stage cp.async pipeline (was 3), 192KB smem    [latency absorption]
//  - bias preloaded to registers before mainloop
//  - converts merged into one kernel launch
// ============================================================================

#define DIM      2048
#define M_TOTAL  8192
#define BM       128
#define BN       256
#define BK       64
#define THREADS  512
#define STAGES   4
#define KITERS   (DIM / BK)          // 32

// fp16 scratch (allocation-free: __device__ globals)
__device__ __half g_Xh[(size_t)M_TOTAL * DIM];   // 32 MB
__device__ __half g_Wh[(size_t)DIM * DIM];       //  8 MB

// smem: per stage A[128x64]f16 = 16KB, B[256x64]f16 = 32KB
#define A_BYTES     16384
#define STAGE_BYTES 49152
#define SMEM_BYTES  (STAGES * STAGE_BYTES)       // 196608

// ---------------------------------------------------------------------------
__device__ __forceinline__ uint32_t smem_u32(const void* p) {
    uint32_t a;
    asm("{ .reg .u64 t; cvta.to.shared.u64 t, %1; cvt.u32.u64 %0, t; }"
        : "=r"(a) : "l"(p));
    return a;
}
__device__ __forceinline__ uint32_t swz(uint32_t b) {   // SW128: rows of 128B
    return b ^ ((b >> 3) & 0x70);
}
__device__ __forceinline__ void cp16(uint32_t dst, const void* src) {
    asm volatile("cp.async.cg.shared.global [%0], [%1], 16;"
                 :: "r"(dst), "l"(src));
}
#define CP_COMMIT() asm volatile("cp.async.commit_group;" ::: "memory")
#define CP_WAIT2()  asm volatile("cp.async.wait_group %0;" :: "n"(STAGES - 2) : "memory")

#define LDSM4(r0, r1, r2, r3, addr) \
    asm volatile("ldmatrix.sync.aligned.m8n8.x4.shared.b16 {%0,%1,%2,%3}, [%4];" \
                 : "=r"(r0), "=r"(r1), "=r"(r2), "=r"(r3) : "r"(addr))

#define MMA16816(c0, c1, c2, c3, a0, a1, a2, a3, b0, b1) \
    asm volatile("mma.sync.aligned.m16n8k16.row.col.f32.f16.f16.f32 " \
                 "{%0,%1,%2,%3}, {%4,%5,%6,%7}, {%8,%9}, {%0,%1,%2,%3};" \
                 : "+f"(c0), "+f"(c1), "+f"(c2), "+f"(c3) \
                 : "r"(a0), "r"(a1), "r"(a2), "r"(a3), "r"(b0), "r"(b1))

// ============================================================================
// fp32 -> fp16 converter (x and W fused into one launch)
// ============================================================================
#define NX4 ((M_TOTAL * DIM) / 4)    // 4,194,304
#define NW4 ((DIM * DIM) / 4)        // 1,048,576

__global__ void __launch_bounds__(256) conv_kernel(const float4* __restrict__ x,
                                                   const float4* __restrict__ W) {
    int i = blockIdx.x * 256 + threadIdx.x;
    const float4* src;
    uint2* dst;
    int j;
    if (i < NX4) {
        src = x;  dst = reinterpret_cast<uint2*>(g_Xh);  j = i;
    } else {
        src = W;  dst = reinterpret_cast<uint2*>(g_Wh);  j = i - NX4;
    }
    float4 v = src[j];
    __half2 lo = __floats2half2_rn(v.x, v.y);
    __half2 hi = __floats2half2_rn(v.z, v.w);
    uint2 p;
    p.x = *reinterpret_cast<uint32_t*>(&lo);
    p.y = *reinterpret_cast<uint32_t*>(&hi);
    dst[j] = p;
}

// ============================================================================
// GEMM: 128x256 CTA tile, 16 warps (2 M x 8 N), warp tile 64x32,
// 4-stage cp.async pipeline, one barrier per K-iter, SW128 smem,
// ldmatrix + mma.sync fp16, fp32 accumulate, bias in registers.
// ============================================================================
__device__ __forceinline__ void issue_stage(uint32_t sbase, int s, int kc,
                                            int mBase, int nBase, int tid) {
    const uint32_t st = sbase + (uint32_t)s * STAGE_BYTES;
    const __half* Ag = g_Xh + (size_t)mBase * DIM + kc;
    const __half* Bg = g_Wh + (size_t)nBase * DIM + kc;
    // A: 128 rows x 128B = 1024 x 16B chunks; 512 thr x 2
    #pragma unroll
    for (int i = 0; i < 2; i++) {
        int g = i * THREADS + tid;
        int row = g >> 3, c = g & 7;
        cp16(st + swz((uint32_t)(row * 128 + c * 16)),
             Ag + (size_t)row * DIM + c * 8);
    }
    // B: 256 rows x 128B = 2048 x 16B chunks; 512 thr x 4
    #pragma unroll
    for (int i = 0; i < 4; i++) {
        int g = i * THREADS + tid;
        int row = g >> 3, c = g & 7;
        cp16(st + A_BYTES + swz((uint32_t)(row * 128 + c * 16)),
             Bg + (size_t)row * DIM + c * 8);
    }
}

__global__ void __launch_bounds__(THREADS, 1) gemm_fp16_kernel(
    float* __restrict__ out, const float* __restrict__ bias)
{
    extern __shared__ __align__(1024) char smem[];
    const uint32_t sbase = smem_u32(smem);
    const int tid  = threadIdx.x;
    const int lane = tid & 31;
    const int wid  = tid >> 5;
    const int warp_m = wid & 1;        // 2 warps in M
    const int warp_n = wid >> 1;       // 8 warps in N

    const int nBase = blockIdx.x * BN;
    const int mBase = blockIdx.y * BM;

    // bias per thread: 4 float2 (one per nb), constant across mt
    const int n0 = nBase + warp_n * 32 + (lane & 3) * 2;
    float2 bb[4];
    #pragma unroll
    for (int nb = 0; nb < 4; nb++)
        bb[nb] = __ldg(reinterpret_cast<const float2*>(bias + n0 + nb * 8));

    float c[4][4][4];                  // [mt][nb][4] = 64 fp32 accum
    #pragma unroll
    for (int mt = 0; mt < 4; mt++)
        #pragma unroll
        for (int nb = 0; nb < 4; nb++)
            #pragma unroll
            for (int r = 0; r < 4; r++) c[mt][nb][r] = 0.0f;

    // prologue: prefetch stages 0..STAGES-2
    #pragma unroll
    for (int s = 0; s < STAGES - 1; s++) {
        issue_stage(sbase, s, s * BK, mBase, nBase, tid);
        CP_COMMIT();
    }

    // ldmatrix address pieces (byte offsets within the tile)
    const uint32_t a_row  = (uint32_t)(warp_m * 64 + (lane & 15));
    const uint32_t a_blo  = (uint32_t)((lane >> 4) << 4);
    const uint32_t b_row0 = (uint32_t)(warp_n * 32 + ((lane >> 4) << 3) + (lane & 7));
    const uint32_t b_blo  = (uint32_t)(((lane >> 3) & 1) << 4);

    for (int it = 0; it < KITERS; ++it) {
        CP_WAIT2();            // stage `it` resident (STAGES-2 younger pending)
        __syncthreads();       // all warps: stage it visible; iter it-1 reads done

        // overwrite buffer (it-1)%STAGES — safe after the barrier above
        if (it + STAGES - 1 < KITERS)
            issue_stage(sbase, (it + STAGES - 1) % STAGES,
                        (it + STAGES - 1) * BK, mBase, nBase, tid);
        CP_COMMIT();

        const uint32_t aB = sbase + (uint32_t)(it % STAGES) * STAGE_BYTES;
        const uint32_t bB = aB + A_BYTES;

        #pragma unroll
        for (int k16 = 0; k16 < 4; ++k16) {
            uint32_t a[4][4];
            #pragma unroll
            for (int mt = 0; mt < 4; mt++) {
                uint32_t off = swz(((a_row + mt * 16) << 7) + (uint32_t)(k16 * 32) + a_blo);
                LDSM4(a[mt][0], a[mt][1], a[mt][2], a[mt][3], aB + off);
            }
            uint32_t b[2][4];
            #pragma unroll
            for (int p = 0; p < 2; p++) {
                uint32_t off = swz(((b_row0 + p * 16) << 7) + (uint32_t)(k16 * 32) + b_blo);
                LDSM4(b[p][0], b[p][1], b[p][2], b[p][3], bB + off);
            }
            #pragma unroll
            for (int mt = 0; mt < 4; mt++)
                #pragma unroll
                for (int nb = 0; nb < 4; nb++) {
                    MMA16816(c[mt][nb][0], c[mt][nb][1], c[mt][nb][2], c[mt][nb][3],
                             a[mt][0], a[mt][1], a[mt][2], a[mt][3],
                             b[nb >> 1][(nb & 1) * 2], b[nb >> 1][(nb & 1) * 2 + 1]);
                }
        }
        // no trailing barrier: next iter's top barrier provides the guarantee
    }

    // epilogue: c layout per mma tile: rows lane/4 (+8), cols (lane%4)*2 (+1)
    const int m0 = mBase + warp_m * 64 + (lane >> 2);
    #pragma unroll
    for (int mt = 0; mt < 4; mt++) {
        #pragma unroll
        for (int nb = 0; nb < 4; nb++) {
            const int row = m0 + mt * 16;
            const int col = n0 + nb * 8;
            float2 v0, v1;
            v0.x = c[mt][nb][0] + bb[nb].x;  v0.y = c[mt][nb][1] + bb[nb].y;
            v1.x = c[mt][nb][2] + bb[nb].x;  v1.y = c[mt][nb][3] + bb[nb].y;
            *reinterpret_cast<float2*>(out + (size_t)row * DIM + col) = v0;
            *reinterpret_cast<float2*>(out + (size_t)(row + 8) * DIM + col) = v1;
        }
    }
}

// ============================================================================
// kernel_launch — graph-capturable, allocation-free
// ============================================================================
extern "C" void kernel_launch(void* const* d_in, const int* in_sizes, int n_in,
                              void* d_out, int out_size) {
    const float* x = (const float*)d_in[0];   // [4,2048,2048] -> [8192,2048]
    const float* W = (const float*)d_in[1];   // [2048,2048]
    const float* b = (const float*)d_in[2];   // [2048]
    float* out = (float*)d_out;               // [8192,2048]
    (void)in_sizes; (void)n_in; (void)out_size;

    conv_kernel<<<(NX4 + NW4) / 256, 256>>>((const float4*)x, (const float4*)W);

    cudaFuncSetAttribute(gemm_fp16_kernel,
                         cudaFuncAttributeMaxDynamicSharedMemorySize, SMEM_BYTES);
    dim3 grid(DIM / BN, M_TOTAL / BM);        // (8, 64) = 512 CTAs
    gemm_fp16_kernel<<<grid, THREADS, SMEM_BYTES>>>(out, b);
}

// round 4
// speedup vs baseline: 1.2162x; 1.1261x over previous
#include <cuda_runtime.h>
#include <cuda_fp16.h>
#include <cstdint>

// ============================================================================
// out[8192,2048] = x[8192,2048] @ W[2048,2048]^T + b   (fp32 in/out)
//
// Path: fp16 mma.sync.m16n8k16, fp32 accum (tcgen05.ld rejected by plain
// sm_103 ptxas target). rel_err 2.06e-4 verified, threshold 1e-3.
//
// R4 vs R3 (225.7us, GEMM 204us, tensor=56%, occ=25%, 1 CTA/SM):
//  - CTA tile 128x256 -> 128x128, 256 threads, __launch_bounds__(256,2)
//    => 2 CTAs/SM (regs 2x256x128=64K, smem 2x96KB=192KB). Two independent
//    barrier domains interleave on the tensor pipe; bubbles overlap.
//  - warp tile unchanged (64x32, 2x4 warp grid) — addressing identical.
// ============================================================================

#define DIM      2048
#define M_TOTAL  8192
#define BM       128
#define BN       128
#define BK       64
#define THREADS  256
#define STAGES   3
#define KITERS   (DIM / BK)          // 32

// fp16 scratch (allocation-free: __device__ globals)
__device__ __half g_Xh[(size_t)M_TOTAL * DIM];   // 32 MB
__device__ __half g_Wh[(size_t)DIM * DIM];       //  8 MB

// smem: per stage A[128x64]f16 = 16KB, B[128x64]f16 = 16KB
#define A_BYTES     16384
#define STAGE_BYTES 32768
#define SMEM_BYTES  (STAGES * STAGE_BYTES)       // 98304

// ---------------------------------------------------------------------------
__device__ __forceinline__ uint32_t smem_u32(const void* p) {
    uint32_t a;
    asm("{ .reg .u64 t; cvta.to.shared.u64 t, %1; cvt.u32.u64 %0, t; }"
        : "=r"(a) : "l"(p));
    return a;
}
__device__ __forceinline__ uint32_t swz(uint32_t b) {   // SW128: rows of 128B
    return b ^ ((b >> 3) & 0x70);
}
__device__ __forceinline__ void cp16(uint32_t dst, const void* src) {
    asm volatile("cp.async.cg.shared.global [%0], [%1], 16;"
                 :: "r"(dst), "l"(src));
}
#define CP_COMMIT() asm volatile("cp.async.commit_group;" ::: "memory")
#define CP_WAIT()   asm volatile("cp.async.wait_group %0;" :: "n"(STAGES - 2) : "memory")

#define LDSM4(r0, r1, r2, r3, addr) \
    asm volatile("ldmatrix.sync.aligned.m8n8.x4.shared.b16 {%0,%1,%2,%3}, [%4];" \
                 : "=r"(r0), "=r"(r1), "=r"(r2), "=r"(r3) : "r"(addr))

#define MMA16816(c0, c1, c2, c3, a0, a1, a2, a3, b0, b1) \
    asm volatile("mma.sync.aligned.m16n8k16.row.col.f32.f16.f16.f32 " \
                 "{%0,%1,%2,%3}, {%4,%5,%6,%7}, {%8,%9}, {%0,%1,%2,%3};" \
                 : "+f"(c0), "+f"(c1), "+f"(c2), "+f"(c3) \
                 : "r"(a0), "r"(a1), "r"(a2), "r"(a3), "r"(b0), "r"(b1))

// ============================================================================
// fp32 -> fp16 converter (x and W in one launch)
// ============================================================================
#define NX4 ((M_TOTAL * DIM) / 4)    // 4,194,304
#define NW4 ((DIM * DIM) / 4)        // 1,048,576

__global__ void __launch_bounds__(256) conv_kernel(const float4* __restrict__ x,
                                                   const float4* __restrict__ W) {
    int i = blockIdx.x * 256 + threadIdx.x;
    const float4* src;
    uint2* dst;
    int j;
    if (i < NX4) {
        src = x;  dst = reinterpret_cast<uint2*>(g_Xh);  j = i;
    } else {
        src = W;  dst = reinterpret_cast<uint2*>(g_Wh);  j = i - NX4;
    }
    float4 v = src[j];
    __half2 lo = __floats2half2_rn(v.x, v.y);
    __half2 hi = __floats2half2_rn(v.z, v.w);
    uint2 p;
    p.x = *reinterpret_cast<uint32_t*>(&lo);
    p.y = *reinterpret_cast<uint32_t*>(&hi);
    dst[j] = p;
}

// ============================================================================
// GEMM: 128x128 CTA tile, 8 warps (2 M x 4 N), warp tile 64x32,
// 3-stage cp.async pipeline, one barrier per K-iter, SW128 smem,
// ldmatrix + mma.sync fp16, fp32 accumulate, 2 CTAs per SM.
// ============================================================================
__device__ __forceinline__ void issue_stage(uint32_t sbase, int s, int kc,
                                            int mBase, int nBase, int tid) {
    const uint32_t st = sbase + (uint32_t)s * STAGE_BYTES;
    const __half* Ag = g_Xh + (size_t)mBase * DIM + kc;
    const __half* Bg = g_Wh + (size_t)nBase * DIM + kc;
    // A: 128 rows x 128B = 1024 x 16B chunks; 256 thr x 4
    #pragma unroll
    for (int i = 0; i < 4; i++) {
        int g = i * THREADS + tid;
        int row = g >> 3, c = g & 7;
        cp16(st + swz((uint32_t)(row * 128 + c * 16)),
             Ag + (size_t)row * DIM + c * 8);
    }
    // B: 128 rows x 128B = 1024 x 16B chunks; 256 thr x 4
    #pragma unroll
    for (int i = 0; i < 4; i++) {
        int g = i * THREADS + tid;
        int row = g >> 3, c = g & 7;
        cp16(st + A_BYTES + swz((uint32_t)(row * 128 + c * 16)),
             Bg + (size_t)row * DIM + c * 8);
    }
}

__global__ void __launch_bounds__(THREADS, 2) gemm_fp16_kernel(
    float* __restrict__ out, const float* __restrict__ bias)
{
    extern __shared__ __align__(1024) char smem[];
    const uint32_t sbase = smem_u32(smem);
    const int tid  = threadIdx.x;
    const int lane = tid & 31;
    const int wid  = tid >> 5;
    const int warp_m = wid & 1;        // 2 warps in M
    const int warp_n = wid >> 1;       // 4 warps in N

    const int nBase = blockIdx.x * BN;
    const int mBase = blockIdx.y * BM;

    // bias per thread: 4 float2 (one per nb), constant across mt
    const int n0 = nBase + warp_n * 32 + (lane & 3) * 2;
    float2 bb[4];
    #pragma unroll
    for (int nb = 0; nb < 4; nb++)
        bb[nb] = __ldg(reinterpret_cast<const float2*>(bias + n0 + nb * 8));

    float c[4][4][4];                  // [mt][nb][4] = 64 fp32 accum
    #pragma unroll
    for (int mt = 0; mt < 4; mt++)
        #pragma unroll
        for (int nb = 0; nb < 4; nb++)
            #pragma unroll
            for (int r = 0; r < 4; r++) c[mt][nb][r] = 0.0f;

    // prologue: prefetch stages 0..STAGES-2
    #pragma unroll
    for (int s = 0; s < STAGES - 1; s++) {
        issue_stage(sbase, s, s * BK, mBase, nBase, tid);
        CP_COMMIT();
    }

    // ldmatrix address pieces (byte offsets within the tile)
    const uint32_t a_row  = (uint32_t)(warp_m * 64 + (lane & 15));
    const uint32_t a_blo  = (uint32_t)((lane >> 4) << 4);
    const uint32_t b_row0 = (uint32_t)(warp_n * 32 + ((lane >> 4) << 3) + (lane & 7));
    const uint32_t b_blo  = (uint32_t)(((lane >> 3) & 1) << 4);

    for (int it = 0; it < KITERS; ++it) {
        CP_WAIT();             // stage `it` resident (STAGES-2 younger pending)
        __syncthreads();       // stage it visible; iter it-1 reads done

        // overwrite buffer (it-1)%STAGES — safe after the barrier above
        if (it + STAGES - 1 < KITERS)
            issue_stage(sbase, (it + STAGES - 1) % STAGES,
                        (it + STAGES - 1) * BK, mBase, nBase, tid);
        CP_COMMIT();

        const uint32_t aB = sbase + (uint32_t)(it % STAGES) * STAGE_BYTES;
        const uint32_t bB = aB + A_BYTES;

        #pragma unroll
        for (int k16 = 0; k16 < 4; ++k16) {
            uint32_t a[4][4];
            #pragma unroll
            for (int mt = 0; mt < 4; mt++) {
                uint32_t off = swz(((a_row + mt * 16) << 7) + (uint32_t)(k16 * 32) + a_blo);
                LDSM4(a[mt][0], a[mt][1], a[mt][2], a[mt][3], aB + off);
            }
            uint32_t b[2][4];
            #pragma unroll
            for (int p = 0; p < 2; p++) {
                uint32_t off = swz(((b_row0 + p * 16) << 7) + (uint32_t)(k16 * 32) + b_blo);
                LDSM4(b[p][0], b[p][1], b[p][2], b[p][3], bB + off);
            }
            #pragma unroll
            for (int mt = 0; mt < 4; mt++)
                #pragma unroll
                for (int nb = 0; nb < 4; nb++) {
                    MMA16816(c[mt][nb][0], c[mt][nb][1], c[mt][nb][2], c[mt][nb][3],
                             a[mt][0], a[mt][1], a[mt][2], a[mt][3],
                             b[nb >> 1][(nb & 1) * 2], b[nb >> 1][(nb & 1) * 2 + 1]);
                }
        }
        // no trailing barrier: next iter's top barrier provides the guarantee
    }

    // epilogue: c layout per mma tile: rows lane/4 (+8), cols (lane%4)*2 (+1)
    const int m0 = mBase + warp_m * 64 + (lane >> 2);
    #pragma unroll
    for (int mt = 0; mt < 4; mt++) {
        #pragma unroll
        for (int nb = 0; nb < 4; nb++) {
            const int row = m0 + mt * 16;
            const int col = n0 + nb * 8;
            float2 v0, v1;
            v0.x = c[mt][nb][0] + bb[nb].x;  v0.y = c[mt][nb][1] + bb[nb].y;
            v1.x = c[mt][nb][2] + bb[nb].x;  v1.y = c[mt][nb][3] + bb[nb].y;
            *reinterpret_cast<float2*>(out + (size_t)row * DIM + col) = v0;
            *reinterpret_cast<float2*>(out + (size_t)(row + 8) * DIM + col) = v1;
        }
    }
}

// ============================================================================
// kernel_launch — graph-capturable, allocation-free
// ============================================================================
extern "C" void kernel_launch(void* const* d_in, const int* in_sizes, int n_in,
                              void* d_out, int out_size) {
    const float* x = (const float*)d_in[0];   // [4,2048,2048] -> [8192,2048]
    const float* W = (const float*)d_in[1];   // [2048,2048]
    const float* b = (const float*)d_in[2];   // [2048]
    float* out = (float*)d_out;               // [8192,2048]
    (void)in_sizes; (void)n_in; (void)out_size;

    conv_kernel<<<(NX4 + NW4) / 256, 256>>>((const float4*)x, (const float4*)W);

    cudaFuncSetAttribute(gemm_fp16_kernel,
                         cudaFuncAttributeMaxDynamicSharedMemorySize, SMEM_BYTES);
    dim3 grid(DIM / BN, M_TOTAL / BM);        // (16, 64) = 1024 CTAs
    gemm_fp16_kernel<<<grid, THREADS, SMEM_BYTES>>>(out, b);
}